// round 10
// baseline (speedup 1.0000x reference)
#include <cuda_runtime.h>
#include <cstdint>

#define DIM 128
#define LAPLACE_C 0.456f
#define EPS 1e-8f
#define INV_SQRT_DIM 0.08838834764831845f /* 1/sqrt(128) */

__device__ uint32_t g_smask[4];

__device__ __forceinline__ float sign_xor(float f, uint32_t bit /*0 or 0x80000000*/) {
    return __uint_as_float(__float_as_uint(f) ^ bit);
}

// Pack signs[d] < 0.5 into 4 ballot words (bit d of word d/32).
__global__ void pack_signs_kernel(const float* __restrict__ signs) {
    const int d = threadIdx.x;               // 0..127
    const uint32_t b = __ballot_sync(0xffffffffu, signs[d] < 0.5f);
    if ((d & 31) == 0) g_smask[d >> 5] = b;
}

__global__ __launch_bounds__(256, 6) void turboquant_kernel(
    const float* __restrict__ x,
    float* __restrict__ out,
    int nrows)
{
    const int lane = threadIdx.x & 31;
    const int t    = lane & 7;                 // thread-in-row (8 threads/row)
    const int warp = (blockIdx.x * blockDim.x + threadIdx.x) >> 5;
    const int row  = warp * 4 + (lane >> 3);   // 4 rows per warp
    if (row >= nrows) return;

    // ---- per-thread sign nibbles: element (j,i) -> index j*32 + t*4 + i ----
    const uint4 sm = *reinterpret_cast<const uint4*>(g_smask);
    uint32_t nib[4];
    nib[0] = (sm.x >> (t * 4)) & 0xF;
    nib[1] = (sm.y >> (t * 4)) & 0xF;
    nib[2] = (sm.z >> (t * 4)) & 0xF;
    nib[3] = (sm.w >> (t * 4)) & 0xF;

    // ---- load 16 elements (4 fully-coalesced float4 loads), apply signs ----
    const float4* xr = reinterpret_cast<const float4*>(x) + (size_t)row * 32;
    float v[4][4];
#pragma unroll
    for (int j = 0; j < 4; j++) {
        float4 xv = __ldg(xr + j * 8 + t);
        v[j][0] = sign_xor(xv.x, (nib[j] & 1u) << 31);
        v[j][1] = sign_xor(xv.y, ((nib[j] >> 1) & 1u) << 31);
        v[j][2] = sign_xor(xv.z, ((nib[j] >> 2) & 1u) << 31);
        v[j][3] = sign_xor(xv.w, ((nib[j] >> 3) & 1u) << 31);
    }

    // ================= forward FWHT (fp32, unnormalized) ====================
    // local bits 0,1 (i within float4)
#pragma unroll
    for (int j = 0; j < 4; j++) {
        float b0 = v[j][0] + v[j][1], b1 = v[j][0] - v[j][1];
        float b2 = v[j][2] + v[j][3], b3 = v[j][2] - v[j][3];
        v[j][0] = b0 + b2; v[j][1] = b1 + b3;
        v[j][2] = b0 - b2; v[j][3] = b1 - b3;
    }
    // cross-lane bits 2,3,4 -> lane xor masks 1,2,4
#pragma unroll
    for (int m = 1; m <= 4; m <<= 1) {
        const float c = (lane & m) ? -1.0f : 1.0f;
#pragma unroll
        for (int j = 0; j < 4; j++)
#pragma unroll
            for (int i = 0; i < 4; i++) {
                float p = __shfl_xor_sync(0xffffffffu, v[j][i], m);
                v[j][i] = fmaf(v[j][i], c, p);
            }
    }
    // local bits 5,6 (j across float4s)
#pragma unroll
    for (int i = 0; i < 4; i++) {
        float b0 = v[0][i] + v[1][i], b1 = v[0][i] - v[1][i];
        float b2 = v[2][i] + v[3][i], b3 = v[2][i] - v[3][i];
        v[0][i] = b0 + b2; v[1][i] = b1 + b3;
        v[2][i] = b0 - b2; v[3][i] = b1 - b3;
    }

    // ================= row stats (8-lane reduction serves 4 rows) ===========
    float ss = 0.0f, sa = 0.0f;
#pragma unroll
    for (int j = 0; j < 4; j++)
#pragma unroll
        for (int i = 0; i < 4; i++) {
            ss = fmaf(v[j][i], v[j][i], ss);
            sa += fabsf(v[j][i]);
        }
#pragma unroll
    for (int m = 1; m <= 4; m <<= 1) {
        ss += __shfl_xor_sync(0xffffffffu, ss, m);
        sa += __shfl_xor_sync(0xffffffffu, sa, m);
    }

    const float norm   = sqrtf(ss) * INV_SQRT_DIM;
    const float inv_ne = 1.0f / (norm + EPS);
    const float scale  = LAPLACE_C * (1.0f / (float)DIM) * sa * inv_ne;  // C·mean|u|
    const float kk     = inv_ne / (scale + EPS);             // q = rint(raw*kk)
    const float fin    = scale * norm * (1.0f / (float)DIM); // deq·(1/D)

    // ======== quantize to int, pack pairs into s16x2 words ==================
    // w[j][0] = [q(i=0) | q(i=1)<<16],  w[j][1] = [q(i=2) | q(i=3)<<16]
    uint32_t w[4][2];
#pragma unroll
    for (int j = 0; j < 4; j++) {
        int q0 = (int)fminf(7.0f, fmaxf(-8.0f, rintf(v[j][0] * kk)));
        int q1 = (int)fminf(7.0f, fmaxf(-8.0f, rintf(v[j][1] * kk)));
        int q2 = (int)fminf(7.0f, fmaxf(-8.0f, rintf(v[j][2] * kk)));
        int q3 = (int)fminf(7.0f, fmaxf(-8.0f, rintf(v[j][3] * kk)));
        w[j][0] = ((uint32_t)q0 & 0xFFFFu) | ((uint32_t)q1 << 16);
        w[j][1] = ((uint32_t)q2 & 0xFFFFu) | ((uint32_t)q3 << 16);
    }

    // ================= inverse FWHT on packed s16x2 integers ================
    // bit 0: intra-word butterfly [a,b] -> [a+b, a-b]
#pragma unroll
    for (int j = 0; j < 4; j++)
#pragma unroll
        for (int k = 0; k < 2; k++) {
            uint32_t sw = __byte_perm(w[j][k], w[j][k], 0x1032);  // [b,a]
            uint32_t s  = __vadd2(w[j][k], sw);                   // [a+b, *]
            uint32_t d  = __vsub2(w[j][k], sw);                   // [a-b, *]
            w[j][k] = __byte_perm(s, d, 0x5410);                  // [a+b, a-b]
        }
    // bit 1: butterfly between word 0 and word 1 ((0,2),(1,3))
#pragma unroll
    for (int j = 0; j < 4; j++) {
        uint32_t a = __vadd2(w[j][0], w[j][1]);
        uint32_t b = __vsub2(w[j][0], w[j][1]);
        w[j][0] = a; w[j][1] = b;
    }
    // cross-lane bits 2,3,4 (24 shuffles instead of 48)
#pragma unroll
    for (int m = 1; m <= 4; m <<= 1) {
        const bool neg = (lane & m) != 0;
#pragma unroll
        for (int j = 0; j < 4; j++)
#pragma unroll
            for (int k = 0; k < 2; k++) {
                uint32_t p = __shfl_xor_sync(0xffffffffu, w[j][k], m);
                w[j][k] = neg ? __vsub2(p, w[j][k]) : __vadd2(w[j][k], p);
            }
    }
    // bits 5,6 (j across words)
#pragma unroll
    for (int k = 0; k < 2; k++) {
        uint32_t b0 = __vadd2(w[0][k], w[1][k]), b1 = __vsub2(w[0][k], w[1][k]);
        uint32_t b2 = __vadd2(w[2][k], w[3][k]), b3 = __vsub2(w[2][k], w[3][k]);
        w[0][k] = __vadd2(b0, b2); w[1][k] = __vadd2(b1, b3);
        w[2][k] = __vsub2(b0, b2); w[3][k] = __vsub2(b1, b3);
    }

    // ---- unpack, scale, re-apply sign, coalesced float4 store ----
    float4* orow = reinterpret_cast<float4*>(out) + (size_t)row * 32;
#pragma unroll
    for (int j = 0; j < 4; j++) {
        int q0 = ((int)(w[j][0] << 16)) >> 16;
        int q1 = ((int)w[j][0]) >> 16;
        int q2 = ((int)(w[j][1] << 16)) >> 16;
        int q3 = ((int)w[j][1]) >> 16;
        float4 ov;
        ov.x = sign_xor((float)q0 * fin, (nib[j] & 1u) << 31);
        ov.y = sign_xor((float)q1 * fin, ((nib[j] >> 1) & 1u) << 31);
        ov.z = sign_xor((float)q2 * fin, ((nib[j] >> 2) & 1u) << 31);
        ov.w = sign_xor((float)q3 * fin, ((nib[j] >> 3) & 1u) << 31);
        orow[j * 8 + t] = ov;
    }
}

extern "C" void kernel_launch(void* const* d_in, const int* in_sizes, int n_in,
                              void* d_out, int out_size)
{
    const float* x     = (const float*)d_in[0];
    const float* signs = (const float*)d_in[1];
    float* out         = (float*)d_out;

    const int nrows = in_sizes[0] / DIM;           // 524288
    pack_signs_kernel<<<1, DIM>>>(signs);
    const int rows_per_block = 32;                 // 8 warps * 4 rows
    const int blocks = (nrows + rows_per_block - 1) / rows_per_block;
    turboquant_kernel<<<blocks, 256>>>(x, out, nrows);
}

// round 15
// speedup vs baseline: 1.0235x; 1.0235x over previous
#include <cuda_runtime.h>
#include <cstdint>

#define DIM 128
#define LAPLACE_C 0.456f
#define EPS 1e-8f
#define INV_SQRT_DIM 0.08838834764831845f /* 1/sqrt(128) */
#define MAGIC 12582912.0f                 /* 1.5 * 2^23 */

__device__ uint32_t g_smask[4];

__device__ __forceinline__ float sign_xor(float f, uint32_t bit /*0 or 0x80000000*/) {
    return __uint_as_float(__float_as_uint(f) ^ bit);
}

// Pack signs[d] < 0.5 into 4 ballot words (bit d of word d/32).
__global__ void pack_signs_kernel(const float* __restrict__ signs) {
    const int d = threadIdx.x;               // 0..127
    const uint32_t b = __ballot_sync(0xffffffffu, signs[d] < 0.5f);
    if ((d & 31) == 0) g_smask[d >> 5] = b;
}

__global__ __launch_bounds__(256, 5) void turboquant_kernel(
    const float* __restrict__ x,
    float* __restrict__ out,
    int nrows)
{
    const int lane = threadIdx.x & 31;
    const int t    = lane & 7;                 // thread-in-row (8 threads/row)
    const int warp = (blockIdx.x * blockDim.x + threadIdx.x) >> 5;
    const int row  = warp * 4 + (lane >> 3);   // 4 rows per warp
    if (row >= nrows) return;

    // ---- per-thread sign nibbles: element (j,i) -> index j*32 + t*4 + i ----
    const uint4 sm = *reinterpret_cast<const uint4*>(g_smask);
    uint32_t nib[4];
    nib[0] = (sm.x >> (t * 4)) & 0xF;
    nib[1] = (sm.y >> (t * 4)) & 0xF;
    nib[2] = (sm.z >> (t * 4)) & 0xF;
    nib[3] = (sm.w >> (t * 4)) & 0xF;

    // ---- load 16 elements (4 fully-coalesced float4 loads), apply signs ----
    const float4* xr = reinterpret_cast<const float4*>(x) + (size_t)row * 32;
    float v[4][4];
#pragma unroll
    for (int j = 0; j < 4; j++) {
        float4 xv = __ldg(xr + j * 8 + t);
        v[j][0] = sign_xor(xv.x, (nib[j] & 1u) << 31);
        v[j][1] = sign_xor(xv.y, ((nib[j] >> 1) & 1u) << 31);
        v[j][2] = sign_xor(xv.z, ((nib[j] >> 2) & 1u) << 31);
        v[j][3] = sign_xor(xv.w, ((nib[j] >> 3) & 1u) << 31);
    }

    // ================= forward FWHT (fp32, unnormalized) ====================
    // local bits 0,1 (i within float4)
#pragma unroll
    for (int j = 0; j < 4; j++) {
        float b0 = v[j][0] + v[j][1], b1 = v[j][0] - v[j][1];
        float b2 = v[j][2] + v[j][3], b3 = v[j][2] - v[j][3];
        v[j][0] = b0 + b2; v[j][1] = b1 + b3;
        v[j][2] = b0 - b2; v[j][3] = b1 - b3;
    }
    // cross-lane bits 2,3,4 -> lane xor masks 1,2,4
#pragma unroll
    for (int m = 1; m <= 4; m <<= 1) {
        const float c = (lane & m) ? -1.0f : 1.0f;
#pragma unroll
        for (int j = 0; j < 4; j++)
#pragma unroll
            for (int i = 0; i < 4; i++) {
                float p = __shfl_xor_sync(0xffffffffu, v[j][i], m);
                v[j][i] = fmaf(v[j][i], c, p);
            }
    }
    // local bits 5,6 (j across float4s)
#pragma unroll
    for (int i = 0; i < 4; i++) {
        float b0 = v[0][i] + v[1][i], b1 = v[0][i] - v[1][i];
        float b2 = v[2][i] + v[3][i], b3 = v[2][i] - v[3][i];
        v[0][i] = b0 + b2; v[1][i] = b1 + b3;
        v[2][i] = b0 - b2; v[3][i] = b1 - b3;
    }

    // ================= row stats (8-lane reduction serves 4 rows) ===========
    float ss = 0.0f, sa = 0.0f;
#pragma unroll
    for (int j = 0; j < 4; j++)
#pragma unroll
        for (int i = 0; i < 4; i++) {
            ss = fmaf(v[j][i], v[j][i], ss);
            sa += fabsf(v[j][i]);
        }
#pragma unroll
    for (int m = 1; m <= 4; m <<= 1) {
        ss += __shfl_xor_sync(0xffffffffu, ss, m);
        sa += __shfl_xor_sync(0xffffffffu, sa, m);
    }

    const float norm   = sqrtf(ss) * INV_SQRT_DIM;
    const float inv_ne = 1.0f / (norm + EPS);
    const float scale  = LAPLACE_C * (1.0f / (float)DIM) * sa * inv_ne;  // C·mean|u|
    const float kk     = inv_ne / (scale + EPS);             // q = rint(raw*kk)
    const float fin    = scale * norm * (1.0f / (float)DIM); // deq·(1/D)

    // ===== quantize via magic round (FFMA) + clamp in magic space ==========
    // m = rint(v*kk) + MAGIC as float bit pattern; low 16 bits = q as s16.
#pragma unroll
    for (int j = 0; j < 4; j++)
#pragma unroll
        for (int i = 0; i < 4; i++) {
            float q = fmaf(v[j][i], kk, MAGIC);
            q = fminf(MAGIC + 7.0f, fmaxf(MAGIC - 8.0f, q));
            v[j][i] = q;
        }

    // ===== pack pairs (i even, i odd) into s16x2 words with one PRMT each ===
    // w[j][k] = [q(i=2k) | q(i=2k+1)<<16]
    uint32_t w[4][2];
#pragma unroll
    for (int j = 0; j < 4; j++) {
        w[j][0] = __byte_perm(__float_as_uint(v[j][0]), __float_as_uint(v[j][1]), 0x5410);
        w[j][1] = __byte_perm(__float_as_uint(v[j][2]), __float_as_uint(v[j][3]), 0x5410);
    }

    // ================= inverse FWHT on packed s16x2 integers ================
    // bit 0: intra-word butterfly [a,b] -> [a+b, a-b]
#pragma unroll
    for (int j = 0; j < 4; j++)
#pragma unroll
        for (int k = 0; k < 2; k++) {
            uint32_t sw = __byte_perm(w[j][k], w[j][k], 0x1032);  // [b,a]
            uint32_t s  = __vadd2(w[j][k], sw);                   // [a+b, *]
            uint32_t d  = __vsub2(w[j][k], sw);                   // [a-b, *]
            w[j][k] = __byte_perm(s, d, 0x5410);                  // [a+b, a-b]
        }
    // bit 1: butterfly between word 0 and word 1 ((0,2),(1,3))
#pragma unroll
    for (int j = 0; j < 4; j++) {
        uint32_t a = __vadd2(w[j][0], w[j][1]);
        uint32_t b = __vsub2(w[j][0], w[j][1]);
        w[j][0] = a; w[j][1] = b;
    }
    // cross-lane bits 2,3,4 (24 shuffles instead of 48)
#pragma unroll
    for (int m = 1; m <= 4; m <<= 1) {
        const bool neg = (lane & m) != 0;
#pragma unroll
        for (int j = 0; j < 4; j++)
#pragma unroll
            for (int k = 0; k < 2; k++) {
                uint32_t p = __shfl_xor_sync(0xffffffffu, w[j][k], m);
                w[j][k] = neg ? __vsub2(p, w[j][k]) : __vadd2(w[j][k], p);
            }
    }
    // bits 5,6 (j across words)
#pragma unroll
    for (int k = 0; k < 2; k++) {
        uint32_t b0 = __vadd2(w[0][k], w[1][k]), b1 = __vsub2(w[0][k], w[1][k]);
        uint32_t b2 = __vadd2(w[2][k], w[3][k]), b3 = __vsub2(w[2][k], w[3][k]);
        w[0][k] = __vadd2(b0, b2); w[1][k] = __vadd2(b1, b3);
        w[2][k] = __vsub2(b0, b2); w[3][k] = __vsub2(b1, b3);
    }

    // ---- unpack (I2F.S16 H0/H1), scale, re-apply sign, float4 store ----
    float4* orow = reinterpret_cast<float4*>(out) + (size_t)row * 32;
#pragma unroll
    for (int j = 0; j < 4; j++) {
        float f0 = (float)((short)(w[j][0] & 0xFFFFu));
        float f1 = (float)((short)(((int)w[j][0]) >> 16));
        float f2 = (float)((short)(w[j][1] & 0xFFFFu));
        float f3 = (float)((short)(((int)w[j][1]) >> 16));
        float4 ov;
        ov.x = sign_xor(f0 * fin, (nib[j] & 1u) << 31);
        ov.y = sign_xor(f1 * fin, ((nib[j] >> 1) & 1u) << 31);
        ov.z = sign_xor(f2 * fin, ((nib[j] >> 2) & 1u) << 31);
        ov.w = sign_xor(f3 * fin, ((nib[j] >> 3) & 1u) << 31);
        orow[j * 8 + t] = ov;
    }
}

extern "C" void kernel_launch(void* const* d_in, const int* in_sizes, int n_in,
                              void* d_out, int out_size)
{
    const float* x     = (const float*)d_in[0];
    const float* signs = (const float*)d_in[1];
    float* out         = (float*)d_out;

    const int nrows = in_sizes[0] / DIM;           // 524288
    pack_signs_kernel<<<1, DIM>>>(signs);
    const int rows_per_block = 32;                 // 8 warps * 4 rows
    const int blocks = (nrows + rows_per_block - 1) / rows_per_block;
    turboquant_kernel<<<blocks, 256>>>(x, out, nrows);
}